// round 1
// baseline (speedup 1.0000x reference)
#include <cuda_runtime.h>
#include <math.h>

// Problem constants (fixed by reference setup_inputs)
#define BATCH 64
#define Hh 512
#define Ww 512
#define Cc 3
#define NPIX (Hh * Ww)
#define NELEM (NPIX * Cc)
#define NUM_LAYERS 2

#define MAGv  0.5f
#define ENHv  (1.0f + 0.9f * MAGv)   // 1.45
#define FILLv 0.5f

// 201 MB ping-pong scratch + per-image sums (alloc-free rule: __device__ globals)
__device__ float g_buf[(size_t)BATCH * NELEM];
__device__ float g_meansum[BATCH];

__global__ void zero_means_kernel() {
    if (threadIdx.x < BATCH) g_meansum[threadIdx.x] = 0.0f;
}

// Per-image sum, only for images whose op at `layer` is contrast (op==6).
// grid: (64, BATCH), block 256
__global__ void mean_kernel(const float* __restrict__ ext_src, int use_buf,
                            const int* __restrict__ ops, int layer) {
    const int b = blockIdx.y;
    if (ops[b * NUM_LAYERS + layer] != 6) return;
    const float* src = use_buf ? g_buf : ext_src;
    const float* img = src + (size_t)b * NELEM;
    float acc = 0.0f;
    const int stride = gridDim.x * blockDim.x;
    for (int i = blockIdx.x * blockDim.x + threadIdx.x; i < NELEM; i += stride)
        acc += __ldg(&img[i]);
    __shared__ float sh[256];
    sh[threadIdx.x] = acc;
    __syncthreads();
    for (int off = 128; off > 0; off >>= 1) {
        if (threadIdx.x < off) sh[threadIdx.x] += sh[threadIdx.x + off];
        __syncthreads();
    }
    if (threadIdx.x == 0) atomicAdd(&g_meansum[b], sh[0]);
}

__device__ __forceinline__ float tap(const float* __restrict__ img, int yy, int xx, int ch) {
    bool valid = (xx >= 0) & (xx < Ww) & (yy >= 0) & (yy < Hh);
    int yc = min(max(yy, 0), Hh - 1);
    int xc = min(max(xx, 0), Ww - 1);
    float v = __ldg(&img[(yc * Ww + xc) * Cc + ch]);
    return valid ? v : FILLv;
}

__device__ __forceinline__ float clip01(float v) {
    return fminf(fmaxf(v, 0.0f), 1.0f);
}

// grid: (NPIX/256, BATCH), block 256. One thread = one output pixel (3 channels).
__global__ void distort_kernel(const float* __restrict__ ext_src, int src_is_buf,
                               float* __restrict__ ext_dst, int dst_is_buf,
                               const int* __restrict__ ops,
                               const int* __restrict__ signs, int layer) {
    const int b = blockIdx.y;
    const int p = blockIdx.x * blockDim.x + threadIdx.x;   // pixel index
    const int y = p >> 9;       // Ww == 512
    const int x = p & 511;

    const float* src = src_is_buf ? g_buf : ext_src;
    float* dst = dst_is_buf ? g_buf : ext_dst;
    const float* img = src + (size_t)b * NELEM;
    float* out = dst + (size_t)b * NELEM;

    const int op = __ldg(&ops[b * NUM_LAYERS + layer]);
    const float s = 2.0f * (float)__ldg(&signs[b * NUM_LAYERS + layer]) - 1.0f;

    float r0, r1, r2;

    if (op < 5) {
        // ---- affine ops: inverse map about center, bilinear, FILL outside ----
        float A = 1.0f, Bm = 0.0f, TX = 0.0f, Cm = 0.0f, D = 1.0f, TY = 0.0f;
        if (op == 0) {            // rotate
            float th = s * (30.0f * MAGv) * (3.14159265358979323846f / 180.0f);
            float co, si;
            sincosf(th, &si, &co);
            A = co; Bm = si; Cm = -si; D = co;
        } else if (op == 1) {     // shear_x
            Bm = -(s * 0.3f * MAGv);
        } else if (op == 2) {     // shear_y
            Cm = -(s * 0.3f * MAGv);
        } else if (op == 3) {     // trans_x
            TX = -(s * 0.3f * MAGv * (float)Ww);
        } else {                  // trans_y
            TY = -(s * 0.3f * MAGv * (float)Hh);
        }
        const float cx = (Ww - 1) * 0.5f;
        const float cy = (Hh - 1) * 0.5f;
        const float xf = (float)x, yf = (float)y;
        const float xi = A * (xf - cx) + Bm * (yf - cy) + TX + cx;
        const float yi = Cm * (xf - cx) + D * (yf - cy) + TY + cy;
        const float x0 = floorf(xi), y0 = floorf(yi);
        const float wx = xi - x0, wy = yi - y0;
        const int ix0 = (int)x0, iy0 = (int)y0;
        const float w00 = (1.0f - wx) * (1.0f - wy);
        const float w10 = wx * (1.0f - wy);
        const float w01 = (1.0f - wx) * wy;
        const float w11 = wx * wy;
        #pragma unroll
        for (int ch = 0; ch < Cc; ch++) {
            float v00 = tap(img, iy0, ix0, ch);
            float v10 = tap(img, iy0, ix0 + 1, ch);
            float v01 = tap(img, iy0 + 1, ix0, ch);
            float v11 = tap(img, iy0 + 1, ix0 + 1, ch);
            float v = v00 * w00 + v10 * w10 + v01 * w01 + v11 * w11;
            if (ch == 0) r0 = v; else if (ch == 1) r1 = v; else r2 = v;
        }
    } else {
        const float f = (s > 0.0f) ? ENHv : (1.0f / ENHv);
        if (op == 5) {            // brightness: clip(f * img)
            #pragma unroll
            for (int ch = 0; ch < Cc; ch++) {
                float v = clip01(f * __ldg(&img[p * Cc + ch]));
                if (ch == 0) r0 = v; else if (ch == 1) r1 = v; else r2 = v;
            }
        } else if (op == 6) {     // contrast: clip(m + f*(img - m))
            const float m = g_meansum[b] * (1.0f / (float)NELEM);
            #pragma unroll
            for (int ch = 0; ch < Cc; ch++) {
                float v = __ldg(&img[p * Cc + ch]);
                v = clip01(m + f * (v - m));
                if (ch == 0) r0 = v; else if (ch == 1) r1 = v; else r2 = v;
            }
        } else {                  // sharpness: clip(smooth + f*(img - smooth))
            #pragma unroll
            for (int ch = 0; ch < Cc; ch++) {
                // 3x3 kernel [[1,1,1],[1,5,1],[1,1,1]]/13 with edge-clamp padding
                float sm = 0.0f;
                #pragma unroll
                for (int dy = -1; dy <= 1; dy++) {
                    int yc = min(max(y + dy, 0), Hh - 1);
                    #pragma unroll
                    for (int dx = -1; dx <= 1; dx++) {
                        int xc = min(max(x + dx, 0), Ww - 1);
                        float k = (dx == 0 && dy == 0) ? (5.0f / 13.0f) : (1.0f / 13.0f);
                        sm += k * __ldg(&img[(yc * Ww + xc) * Cc + ch]);
                    }
                }
                float v = __ldg(&img[p * Cc + ch]);
                v = clip01(sm + f * (v - sm));
                if (ch == 0) r0 = v; else if (ch == 1) r1 = v; else r2 = v;
            }
        }
    }

    out[p * Cc + 0] = r0;
    out[p * Cc + 1] = r1;
    out[p * Cc + 2] = r2;
}

extern "C" void kernel_launch(void* const* d_in, const int* in_sizes, int n_in,
                              void* d_out, int out_size) {
    const float* images = (const float*)d_in[0];
    const int* op_ids = (const int*)d_in[1];
    const int* sgn = (const int*)d_in[2];
    float* out = (float*)d_out;

    dim3 mgrid(64, BATCH);
    dim3 grid(NPIX / 256, BATCH);

    // Layer 0: d_in -> g_buf
    zero_means_kernel<<<1, 64>>>();
    mean_kernel<<<mgrid, 256>>>(images, 0, op_ids, 0);
    distort_kernel<<<grid, 256>>>(images, 0, nullptr, 1, op_ids, sgn, 0);

    // Layer 1: g_buf -> d_out
    zero_means_kernel<<<1, 64>>>();
    mean_kernel<<<mgrid, 256>>>(nullptr, 1, op_ids, 1);
    distort_kernel<<<grid, 256>>>(nullptr, 1, out, 0, op_ids, sgn, 1);
}